// round 8
// baseline (speedup 1.0000x reference)
#include <cuda_runtime.h>
#include <cuda_fp16.h>
#include <cstdint>

// ============================================================
// out[b,n] = sum_{c,p} x[b,c,p]*mask[p,c,n]*ro[c,n]
//          = A(256 x 82944) @ W(82944 x 2000),  k = p*64+c
//   A[b,k] = fp16(x[b,c,p])                  (pack kernel)
//   W[k,n] = fp16(mask_flat[k,n]*ro[k&63,n]*1024)  (built on the
//            fly inside the GEMM; output scaled by 1/1024)
// GEMM: mma.sync.m16n8k16.f16 (f32 accum) -- the sm_100 generic
//       target rejects tcgen05, so this is the fastest available
//       tensor path under the harness's compile line.
// CTA tile 256(m) x 128(n), KTILE=32, double-buffered cp.async A
// + LDG-prefetch mask -> scale -> STS B.  Grid 16 x 9(split-K)
// = 144 CTAs = one wave.  fp32 partials, then reduce.
// ============================================================

constexpr int BB   = 256;
constexpr int CCH  = 64;
constexpr int PPX  = 1296;
constexpr int NN   = 2000;
constexpr int NPAD = 2048;
constexpr long long KT_TOT = 82944;

constexpr int KSPLIT = 9;
constexpr int KSLICE = 9216;                  // 82944/9, divisible by 64
constexpr int KTILE  = 32;
constexpr int NKT    = KSLICE / KTILE;        // 288
constexpr int NTILE  = 128;
constexpr int NTX    = 16;                    // 2048/128

constexpr int SA = 40;                        // A smem stride (halves): 80B rows, 16B-aligned, ldmatrix-clean
constexpr int SB = 34;                        // B smem stride (halves): 68B rows, conflict-free b32 frag loads
constexpr int A_ST = 256 * SA;                // halves per A stage
constexpr int B_ST = NTILE * SB;              // halves per B stage
constexpr int SM_A_BYTES  = 2 * A_ST * 2;     // 40960
constexpr int SM_B_BYTES  = 2 * B_ST * 2;     // 17408
constexpr int SM_RO_BYTES = 64 * 128 * 4;     // 32768
constexpr int SMEM_TOTAL  = SM_A_BYTES + SM_B_BYTES + SM_RO_BYTES;  // 91136

// ------------- scratch (device globals; no runtime allocs allowed) ----------
__device__ __half g_Ah[(size_t)BB * KT_TOT];               // 42.5 MB
__device__ float  g_part[(size_t)KSPLIT * BB * NPAD];      // 18.9 MB

// ----------------------------- helpers --------------------------------------
__device__ __forceinline__ uint32_t smem_u32(const void* p) {
    uint32_t a;
    asm("{ .reg .u64 t; cvta.to.shared.u64 t, %1; cvt.u32.u64 %0, t; }"
        : "=r"(a) : "l"(p));
    return a;
}
__device__ __forceinline__ uint32_t lds_u32(uint32_t a) {
    uint32_t v;
    asm volatile("ld.shared.b32 %0, [%1];" : "=r"(v) : "r"(a));
    return v;
}
#define STS_U32(addr, v) \
    asm volatile("st.shared.b32 [%0], %1;" :: "r"(addr), "r"(v) : "memory")
#define CP_A16(dst, src) \
    asm volatile("cp.async.cg.shared.global [%0], [%1], 16;" :: "r"(dst), "l"(src))
#define CP_COMMIT() asm volatile("cp.async.commit_group;" ::: "memory")
#define CP_WAIT0()  asm volatile("cp.async.wait_group 0;" ::: "memory")
#define LDSM4(r0, r1, r2, r3, addr) \
    asm volatile("ldmatrix.sync.aligned.m8n8.x4.shared.b16 {%0,%1,%2,%3}, [%4];" \
        : "=r"(r0), "=r"(r1), "=r"(r2), "=r"(r3) : "r"(addr))
#define MMA16816(d0, d1, d2, d3, a0, a1, a2, a3, b0, b1) \
    asm volatile("mma.sync.aligned.m16n8k16.row.col.f32.f16.f16.f32 " \
        "{%0,%1,%2,%3}, {%4,%5,%6,%7}, {%8,%9}, {%0,%1,%2,%3};" \
        : "+f"(d0), "+f"(d1), "+f"(d2), "+f"(d3) \
        : "r"(a0), "r"(a1), "r"(a2), "r"(a3), "r"(b0), "r"(b1))

// ------------------ kernel 1: pack x -> Ah[b][p*64+c] (fp16) ----------------
__global__ void pack_x_kernel(const float* __restrict__ x) {
    __shared__ float s[64][65];
    int b = blockIdx.y;
    int p0 = blockIdx.x * 64;
    int tid = threadIdx.x;
    const float* xb = x + (size_t)b * (CCH * PPX);
    #pragma unroll
    for (int it = 0; it < 16; it++) {
        int t = tid + it * 256;
        int c = t >> 6, i = t & 63, p = p0 + i;
        s[c][i] = (p < PPX) ? xb[c * PPX + p] : 0.f;
    }
    __syncthreads();
    __half* ab = g_Ah + (size_t)b * KT_TOT;
    #pragma unroll
    for (int it = 0; it < 16; it++) {
        int t = tid + it * 256;
        int i = t >> 6, c = t & 63, p = p0 + i;
        if (p < PPX) ab[p * 64 + c] = __float2half_rn(s[c][i]);
    }
}

// ------------------ kernel 2: fused fp16 mma.sync GEMM ----------------------
__global__ void __launch_bounds__(256, 1)
gemm_kernel(const float* __restrict__ mask, const float* __restrict__ ro) {
    extern __shared__ __align__(16) unsigned char smraw[];
    __half* As  = reinterpret_cast<__half*>(smraw);
    __half* Bsm = reinterpret_cast<__half*>(smraw + SM_A_BYTES);
    float*  ros = reinterpret_cast<float*>(smraw + SM_A_BYTES + SM_B_BYTES);

    int tid = threadIdx.x, w = tid >> 5, l = tid & 31;
    int n0 = blockIdx.x * NTILE;
    long long kbase = (long long)blockIdx.z * KSLICE;

    // preload ros[c][n'] = ro[c][n0+n'] * 1024  (64 x 128 fp32 = 32 KB)
    for (int idx = tid; idx < 64 * 32; idx += 256) {
        int c = idx >> 5, nq4 = idx & 31;
        float4 v = make_float4(0.f, 0.f, 0.f, 0.f);
        if (n0 + 4 * nq4 < NN) {
            float4 t = *reinterpret_cast<const float4*>(ro + (size_t)c * NN + n0 + 4 * nq4);
            v = make_float4(t.x * 1024.f, t.y * 1024.f, t.z * 1024.f, t.w * 1024.f);
        }
        reinterpret_cast<float4*>(ros)[idx] = v;
    }

    // B-build mapping: thread (nq, kq) covers n = n0+4nq..+3, k rows 2kq,2kq+1 (+16)
    int nq = tid & 31, kq = (tid >> 5) & 7;
    bool val = (n0 + 4 * nq) < NN;
    const float* mb = mask + kbase * NN + (n0 + 4 * nq);

    // A cp.async mapping: thread owns row m = tid (64B = 4 x 16B chunks per tile)
    const __half* arow = g_Ah + (size_t)tid * KT_TOT + kbase;
    uint32_t sbase = smem_u32(As);
    uint32_t adst  = sbase + (uint32_t)tid * (SA * 2);

    float4 mr[4];
    auto ldmask = [&](int kt) {
        #pragma unroll
        for (int it = 0; it < 2; it++) {
            int k0 = kt * KTILE + 2 * kq + 16 * it;
            if (val) {
                mr[2 * it]     = *reinterpret_cast<const float4*>(mb + (size_t)k0 * NN);
                mr[2 * it + 1] = *reinterpret_cast<const float4*>(mb + (size_t)(k0 + 1) * NN);
            } else {
                mr[2 * it] = make_float4(0.f, 0.f, 0.f, 0.f);
                mr[2 * it + 1] = make_float4(0.f, 0.f, 0.f, 0.f);
            }
        }
    };

    ldmask(0);
    #pragma unroll
    for (int c4 = 0; c4 < 4; c4++)
        CP_A16(adst + c4 * 16, arow + c4 * 8);
    CP_COMMIT();

    __syncthreads();   // ros visible before first B build

    // fragment addressing
    int wm = (w & 3) * 64, wn = (w >> 2) * 64;
    uint32_t aLdsm = sbase + (uint32_t)(((wm + (l & 15)) * SA + ((l & 16) ? 8 : 0)) * 2);
    uint32_t bbase = smem_u32(Bsm);
    uint32_t bfrag0 = bbase + (uint32_t)((wn + (l >> 2)) * SB * 2) + (uint32_t)(4 * (l & 3));

    float acc[4][8][4];
    #pragma unroll
    for (int i = 0; i < 4; i++)
        #pragma unroll
        for (int j = 0; j < 8; j++)
            #pragma unroll
            for (int q = 0; q < 4; q++) acc[i][j][q] = 0.f;

    for (int kt = 0; kt < NKT; kt++) {
        int s = kt & 1;

        // ---- build B tile (scale + fp16 convert + transpose to [n][k]) ----
        {
            uint32_t bd = bbase + (uint32_t)(s * (B_ST * 2)) + (uint32_t)(4 * nq * SB * 2);
            const float* rp = ros + ((kt & 1) ? 32 * 128 : 0) + 4 * nq;
            #pragma unroll
            for (int it = 0; it < 2; it++) {
                int k0 = 2 * kq + 16 * it;
                float4 r0 = *reinterpret_cast<const float4*>(rp + k0 * 128);
                float4 r1 = *reinterpret_cast<const float4*>(rp + (k0 + 1) * 128);
                float4 w0 = mr[2 * it], w1 = mr[2 * it + 1];
                __half2 h0 = __floats2half2_rn(w0.x * r0.x, w1.x * r1.x);
                __half2 h1 = __floats2half2_rn(w0.y * r0.y, w1.y * r1.y);
                __half2 h2 = __floats2half2_rn(w0.z * r0.z, w1.z * r1.z);
                __half2 h3 = __floats2half2_rn(w0.w * r0.w, w1.w * r1.w);
                uint32_t a0 = bd + (uint32_t)(k0 * 2);
                STS_U32(a0,              *reinterpret_cast<uint32_t*>(&h0));
                STS_U32(a0 + SB * 2,     *reinterpret_cast<uint32_t*>(&h1));
                STS_U32(a0 + 2 * SB * 2, *reinterpret_cast<uint32_t*>(&h2));
                STS_U32(a0 + 3 * SB * 2, *reinterpret_cast<uint32_t*>(&h3));
            }
        }

        if (kt + 1 < NKT) ldmask(kt + 1);     // prefetch next mask tile into regs
        CP_WAIT0();                            // A[s] resident
        __syncthreads();                       // B[s] visible; prev-iter readers done

        if (kt + 1 < NKT) {                    // next A tile into other buffer
            uint32_t d2 = adst + (uint32_t)((s ^ 1) * (A_ST * 2));
            const __half* src = arow + (size_t)(kt + 1) * KTILE;
            #pragma unroll
            for (int c4 = 0; c4 < 4; c4++)
                CP_A16(d2 + c4 * 16, src + c4 * 8);
            CP_COMMIT();
        }

        // ---- MMA: warp tile 64(m) x 64(n), k32 = 2 ksteps of 16 ----------
        uint32_t aS = aLdsm + (uint32_t)(s * (A_ST * 2));
        uint32_t bS = bfrag0 + (uint32_t)(s * (B_ST * 2));
        #pragma unroll
        for (int ks = 0; ks < 2; ks++) {
            uint32_t af[4][4];
            #pragma unroll
            for (int i = 0; i < 4; i++) {
                LDSM4(af[i][0], af[i][1], af[i][2], af[i][3],
                      aS + (uint32_t)(i * 16 * SA * 2) + (uint32_t)(ks * 32));
            }
            #pragma unroll
            for (int j = 0; j < 8; j++) {
                uint32_t ba = bS + (uint32_t)(j * 8 * SB * 2) + (uint32_t)(ks * 32);
                uint32_t b0 = lds_u32(ba);
                uint32_t b1 = lds_u32(ba + 16);
                #pragma unroll
                for (int i = 0; i < 4; i++)
                    MMA16816(acc[i][j][0], acc[i][j][1], acc[i][j][2], acc[i][j][3],
                             af[i][0], af[i][1], af[i][2], af[i][3], b0, b1);
            }
        }
    }

    // ---- epilogue: fp32 partials ------------------------------------------
    float* __restrict__ part = g_part + (size_t)blockIdx.z * BB * NPAD;
    int r0 = l >> 2, cq = 2 * (l & 3);
    #pragma unroll
    for (int i = 0; i < 4; i++) {
        #pragma unroll
        for (int j = 0; j < 8; j++) {
            int m = wm + 16 * i + r0;
            int n = wn + 8 * j + cq + n0;
            *reinterpret_cast<float2*>(part + (size_t)m * NPAD + n) =
                make_float2(acc[i][j][0], acc[i][j][1]);
            *reinterpret_cast<float2*>(part + (size_t)(m + 8) * NPAD + n) =
                make_float2(acc[i][j][2], acc[i][j][3]);
        }
    }
}

// ------------------ kernel 3: reduce partials -> out (x 1/1024) -------------
__global__ void reduce_kernel(float* __restrict__ out) {
    // one thread -> 4 consecutive n of one b row (vectorized partial reads)
    int id = blockIdx.x * 256 + threadIdx.x;          // id indexes (b, n4)
    int b = id / (NPAD / 4), n4 = id % (NPAD / 4);
    if (b >= BB) return;
    int n = n4 * 4;
    float4 s = make_float4(0.f, 0.f, 0.f, 0.f);
    #pragma unroll
    for (int ks = 0; ks < KSPLIT; ks++) {
        const float4 v = *reinterpret_cast<const float4*>(
            g_part + (size_t)ks * BB * NPAD + (size_t)b * NPAD + n);
        s.x += v.x; s.y += v.y; s.z += v.z; s.w += v.w;
    }
    const float inv = 1.f / 1024.f;
    float* o = out + (size_t)b * NN;
    if (n + 3 < NN) {
        o[n] = s.x * inv; o[n + 1] = s.y * inv; o[n + 2] = s.z * inv; o[n + 3] = s.w * inv;
    } else {
        if (n < NN)     o[n]     = s.x * inv;
        if (n + 1 < NN) o[n + 1] = s.y * inv;
        if (n + 2 < NN) o[n + 2] = s.z * inv;
        if (n + 3 < NN) o[n + 3] = s.w * inv;
    }
}

// ------------------------------- host ---------------------------------------
extern "C" void kernel_launch(void* const* d_in, const int* in_sizes, int n_in,
                              void* d_out, int out_size) {
    const float* x = nullptr;
    const float* mw = nullptr;
    const float* ro = nullptr;
    for (int i = 0; i < n_in; i++) {
        long long sz = in_sizes[i];
        if (sz == (long long)BB * CCH * PPX)      x  = (const float*)d_in[i];
        else if (sz == (long long)PPX * CCH * NN) mw = (const float*)d_in[i];
        else if (sz == (long long)CCH * NN)       ro = (const float*)d_in[i];
    }

    cudaFuncSetAttribute(gemm_kernel, cudaFuncAttributeMaxDynamicSharedMemorySize,
                         SMEM_TOTAL);

    pack_x_kernel<<<dim3(21, BB), 256>>>(x);
    gemm_kernel<<<dim3(NTX, 1, KSPLIT), 256, SMEM_TOTAL>>>(mw, ro);
    reduce_kernel<<<(BB * (NPAD / 4) + 255) / 256, 256>>>((float*)d_out);
}